// round 11
// baseline (speedup 1.0000x reference)
#include <cuda_runtime.h>

// LSTM T=4096, B=2048, I=2, H=4, L=4. Gate order i,f,g,o.
// lane = b*16 + l*4 + j : b = batch-in-warp (2), l = layer (4), j = unit (4).
// Skewed wavefront: body(s) runs layer l at step s-l.
// z pre-activations computed as packed f32x2 gate pairs {i,f} and {g,o} via
// fma.rn.f32x2 (halves FMA instruction count). x/bias contribution (zx) is
// precomputed one body ahead in the shuffle-latency shadow. Layer handoff
// shuffles feed z directly through zeroed weights for l==0 (no SEL merge).
// All activations tanh.approx (sigmoid = 0.5*tanh(x/2)+0.5, weights
// pre-scaled 0.5).

#define TT 4096
#define BB 2048

typedef unsigned long long u64;

__device__ __forceinline__ float tanhx(float x) {
    float y; asm("tanh.approx.f32 %0, %1;" : "=f"(y) : "f"(x)); return y;
}
__device__ __forceinline__ u64 pack2(float lo, float hi) {
    u64 r; asm("mov.b64 %0, {%1, %2};" : "=l"(r) : "f"(lo), "f"(hi)); return r;
}
__device__ __forceinline__ u64 pdup(float v) {
    u64 r; asm("mov.b64 %0, {%1, %1};" : "=l"(r) : "f"(v)); return r;
}
__device__ __forceinline__ void unpack2(u64 v, float& lo, float& hi) {
    asm("mov.b64 {%0, %1}, %2;" : "=f"(lo), "=f"(hi) : "l"(v));
}
__device__ __forceinline__ u64 fma2(u64 a, u64 b, u64 c) {
    u64 d; asm("fma.rn.f32x2 %0, %1, %2, %3;" : "=l"(d) : "l"(a), "l"(b), "l"(c));
    return d;
}
__device__ __forceinline__ u64 mul2(u64 a, u64 b) {
    u64 d; asm("mul.rn.f32x2 %0, %1, %2;" : "=l"(d) : "l"(a), "l"(b));
    return d;
}
__device__ __forceinline__ u64 add2(u64 a, u64 b) {
    u64 d; asm("add.rn.f32x2 %0, %1, %2;" : "=l"(d) : "l"(a), "l"(b));
    return d;
}

__global__ __launch_bounds__(128) void lstm_kernel(
    const float* __restrict__ x,     // (T, B, 2)
    const float* __restrict__ h0g,   // (L, B, 4)
    const float* __restrict__ c0g,   // (L, B, 4)
    const float* __restrict__ Wih0,  // (16, 2)
    const float* __restrict__ Wr,    // (3, 16, 4)  W_ih layers 1..3
    const float* __restrict__ Whh,   // (4, 16, 4)
    const float* __restrict__ bih,   // (4, 16)
    const float* __restrict__ bhh,   // (4, 16)
    float* __restrict__ out)         // ys (T,B,4) ++ hT (L,B,4) ++ cT (L,B,4)
{
    const int lane  = threadIdx.x & 31;
    const int warp  = threadIdx.x >> 5;
    const int b     = lane >> 4;              // batch sub-index in warp 0..1
    const int l     = (lane >> 2) & 3;        // layer 0..3
    const int j     = lane & 3;               // hidden unit 0..3
    const int batch = blockIdx.x * 8 + warp * 2 + b;

    // handoff source lanes (previous layer's quad); width-16 shuffle wraps
    // within the half for l==0 lanes (value is finite, multiplied by 0).
    const int ps0 = lane - 4;
    const int ps1 = (lane - 4) ^ 1;
    const int ps2 = (lane - 4) ^ 2;
    const int ps3 = (lane - 4) ^ 3;

    // ---- packed weights: pair t=0 -> gates (i,f), t=1 -> (g,o) ----
    // sigmoid rows pre-scaled 0.5 (sigma(x) = 0.5*tanh(x/2)+0.5), g row 1.0.
    // handoff-input weights zeroed for l==0; x weights zeroed for l>0.
    u64 winP[2][4], whP[2][4], wxP[2][2], bzP[2];
#pragma unroll
    for (int t = 0; t < 2; t++) {
        const int   rA = (t ? 8 : 0) + j;       // i_j or g_j
        const int   rB = (t ? 12 : 4) + j;      // f_j or o_j
        const float sA = t ? 1.0f : 0.5f;
        const float sB = 0.5f;
#pragma unroll
        for (int m = 0; m < 4; m++) {
            float a = (l > 0) ? Wr[((l - 1) * 16 + rA) * 4 + (j ^ m)] * sA : 0.f;
            float c2 = (l > 0) ? Wr[((l - 1) * 16 + rB) * 4 + (j ^ m)] * sB : 0.f;
            winP[t][m] = pack2(a, c2);
            whP[t][m]  = pack2(Whh[(l * 16 + rA) * 4 + (j ^ m)] * sA,
                               Whh[(l * 16 + rB) * 4 + (j ^ m)] * sB);
        }
#pragma unroll
        for (int m = 0; m < 2; m++) {
            float a = (l == 0) ? Wih0[rA * 2 + m] * sA : 0.f;
            float c2 = (l == 0) ? Wih0[rB * 2 + m] * sB : 0.f;
            wxP[t][m] = pack2(a, c2);
        }
        bzP[t] = pack2((bih[l * 16 + rA] + bhh[l * 16 + rA]) * sA,
                       (bih[l * 16 + rB] + bhh[l * 16 + rB]) * sB);
    }

    // ---- states ----
    float hown[4], c;
    u64 hownP[4], pP[4];
#pragma unroll
    for (int m = 0; m < 4; m++) {
        hown[m]  = h0g[(l * BB + batch) * 4 + (j ^ m)];
        hownP[m] = pdup(hown[m]);
        pP[m]    = pack2(0.f, 0.f);
    }
    c = c0g[(l * BB + batch) * 4 + j];

    float* __restrict__ ys  = out;
    float* __restrict__ hso = out + (size_t)TT * BB * 4;
    float* __restrict__ cso = hso + (size_t)4 * BB * 4;
    float4* __restrict__ ysp = reinterpret_cast<float4*>(ys) + batch - 3 * BB;

    // ---- x stream: rotating regs + running prefetch pointer (depth 3) ----
    const float2* __restrict__ xbase = reinterpret_cast<const float2*>(x) + batch;
    const float2* __restrict__ xend  = xbase + (size_t)TT * BB;
    const float2* __restrict__ xp    = xbase + (size_t)3 * BB;
    float2 xa = xbase[0];
    float2 xn = xbase[(size_t)1 * BB];
    float2 xm = xbase[(size_t)2 * BB];

    // initial zx from x[0]
    u64 zxP0 = fma2(wxP[0][0], pdup(xa.x), fma2(wxP[0][1], pdup(xa.y), bzP[0]));
    u64 zxP1 = fma2(wxP[1][0], pdup(xa.x), fma2(wxP[1][1], pdup(xa.y), bzP[1]));

    auto body = [&](int s, bool masked) {
        bool act = masked ? ((unsigned)(s - l) < (unsigned)TT) : true;

        // ---- packed pre-activations: two independent depth-4 chains/pair ----
        u64 u0 = zxP0, u1 = zxP1;
        u64 v0 = mul2(whP[0][0], hownP[0]);
        u64 v1 = mul2(whP[1][0], hownP[0]);
#pragma unroll
        for (int m = 0; m < 4; m++) {
            u0 = fma2(winP[0][m], pP[m], u0);
            u1 = fma2(winP[1][m], pP[m], u1);
        }
#pragma unroll
        for (int m = 1; m < 4; m++) {
            v0 = fma2(whP[0][m], hownP[m], v0);
            v1 = fma2(whP[1][m], hownP[m], v1);
        }
        float zi, zf, zg, zo;
        unpack2(add2(u0, v0), zi, zf);
        unpack2(add2(u1, v1), zg, zo);

        // ---- activations ----
        float si = fmaf(tanhx(zi), 0.5f, 0.5f);
        float sf = fmaf(tanhx(zf), 0.5f, 0.5f);
        float tg = tanhx(zg);
        float so = fmaf(tanhx(zo), 0.5f, 0.5f);

        float cn = fmaf(sf, c, si * tg);
        float th = tanhx(cn);
        float h  = so * th;

        // ---- 7 independent shuffles, all sourced from h ----
        float h1 = __shfl_xor_sync(0xffffffffu, h, 1);
        float h2 = __shfl_xor_sync(0xffffffffu, h, 2);
        float h3 = __shfl_xor_sync(0xffffffffu, h, 3);
        float p0 = __shfl_sync(0xffffffffu, h, ps0, 16);
        float p1 = __shfl_sync(0xffffffffu, h, ps1, 16);
        float p2 = __shfl_sync(0xffffffffu, h, ps2, 16);
        float p3 = __shfl_sync(0xffffffffu, h, ps3, 16);

        // ---- fill shuffle latency: x rotate + prefetch + next-body zx ----
        xa = xn; xn = xm;
        xm = (xp < xend) ? *xp : xa;
        xp += BB;
        zxP0 = fma2(wxP[0][0], pdup(xa.x), fma2(wxP[0][1], pdup(xa.y), bzP[0]));
        zxP1 = fma2(wxP[1][0], pdup(xa.x), fma2(wxP[1][1], pdup(xa.y), bzP[1]));

        if (act) {
            c = cn;
            hown[0] = h;  hown[1] = h1; hown[2] = h2; hown[3] = h3;
            if (l == 3 && j == 0)
                *ysp = make_float4(h, h1, h2, h3);
        }
        ysp += BB;

        // ---- repack next-body operands ----
        pP[0] = pdup(p0); pP[1] = pdup(p1); pP[2] = pdup(p2); pP[3] = pdup(p3);
        hownP[0] = pdup(hown[0]); hownP[1] = pdup(hown[1]);
        hownP[2] = pdup(hown[2]); hownP[3] = pdup(hown[3]);
    };

    body(0, true); body(1, true); body(2, true);
#pragma unroll 2
    for (int s = 3; s < TT; s++) body(s, false);
    body(TT, true); body(TT + 1, true); body(TT + 2, true);

    // ---- final hT / cT ----
    if (j == 0)   // hown[m] = h_m natural order for j==0
        *reinterpret_cast<float4*>(hso + (l * BB + batch) * 4) =
            make_float4(hown[0], hown[1], hown[2], hown[3]);
    cso[(l * BB + batch) * 4 + j] = c;
}

extern "C" void kernel_launch(void* const* d_in, const int* in_sizes, int n_in,
                              void* d_out, int out_size) {
    (void)in_sizes; (void)n_in; (void)out_size;
    const float* x    = (const float*)d_in[0];
    const float* h0   = (const float*)d_in[1];
    const float* c0   = (const float*)d_in[2];
    const float* Wih0 = (const float*)d_in[3];
    const float* Wr   = (const float*)d_in[4];
    const float* Whh  = (const float*)d_in[5];
    const float* bih  = (const float*)d_in[6];
    const float* bhh  = (const float*)d_in[7];
    // 8 batches per block (4 warps x 2), 256 blocks
    lstm_kernel<<<BB / 8, 128>>>(x, h0, c0, Wih0, Wr, Whh, bih, bhh,
                                 (float*)d_out);
}